// round 7
// baseline (speedup 1.0000x reference)
#include <cuda_runtime.h>

// WENO Black-Scholes stepper, M=80 (81 nodes), 26 Euler steps.
// Each timestep is affine in u: u_{n+1}[k] = sum_{j=-3}^{+2} C_j[k] * u[k+j],
// with C precomputed once from the fixed WENO weights. Lane l owns nodes
// {3l, 3l+1, 3l+2} (lanes 0..26).
// ALL boundary handling is folded into the coefficients:
//   - left ghosts are exactly 0 -> zero the ghost-tap coefficients (lane 0)
//   - node 0 pinned to 0        -> Ca = 0 on lane 0
//   - right ghost u[81]=2u[80]-u[79] -> folded into lane 26's Cb taps
//   - node 80 = BC(t)           -> Cc = 0 on lane 26 + one SEL per step
// Loop body: 5 shuffles, 18 tree-ified FMAs, 1 BC recurrence, 1 select.

#define N_STEPS 26
#define FULLM 0xFFFFFFFFu

// Fused 6-tap coefficients for node k over u[k-3..k+2].
// p = w5 row k, q = w5 row k-1, r = w6 row k-1.
__device__ __forceinline__ void make_coef(const float* p, const float* q,
                                          const float* r, float g1, float g2,
                                          float decay, float* C)
{
    const float i6 = 1.0f / 6.0f;
    // uhat[k] taps over u[k-2..k+2]
    float A_2 = (2.0f * p[0]) * i6;
    float A_1 = (-7.0f * p[0] - p[1]) * i6;
    float A0  = (11.0f * p[0] + 5.0f * p[1] + 2.0f * p[2]) * i6;
    float A1  = (2.0f * p[1] + 5.0f * p[2]) * i6;
    float A2  = (-p[2]) * i6;
    // uhat[k-1] taps over u[k-3..k+1]
    float B_3 = (2.0f * q[0]) * i6;
    float B_2 = (-7.0f * q[0] - q[1]) * i6;
    float B_1 = (11.0f * q[0] + 5.0f * q[1] + 2.0f * q[2]) * i6;
    float B0  = (2.0f * q[1] + 5.0f * q[2]) * i6;
    float B1  = (-q[2]) * i6;
    C[0] = -g1 * B_3;
    C[1] = g1 * (A_2 - B_2) + g2 * r[0];
    C[2] = g1 * (A_1 - B_1) + g2 * (r[1] - 2.0f * r[0]);
    C[3] = g1 * (A0 - B0)   + g2 * (r[0] - 2.0f * r[1] + r[2]) + decay;
    C[4] = g1 * (A1 - B1)   + g2 * (r[1] - 2.0f * r[2]);
    C[5] = g1 * A2          + g2 * r[2];
}

__global__ void __launch_bounds__(32, 1)
weno_bs_kernel(const float* __restrict__ om5,   // (80,3) row-major
               const float* __restrict__ om6,   // (79,3) row-major
               float* __restrict__ out)         // 81 floats
{
    const int l = threadIdx.x;
    const bool act = (l <= 26);

    const float H     = 0.09375f;                 // exact in fp32
    const float DT    = (float)(1.0 / 26.0);
    const float g1    = DT * 0.055f / H;          // DT*ADV/H
    const float g2    = DT * 0.045f / (H * H);    // DT*0.5*sigma^2/H^2
    const float decay = 1.0f - DT * 0.1f;

    // ---- init u0 ----
    float a = 0.f, b = 0.f, c = 0.f;
    if (act) {
        a = fmaxf(50.0f * expf(fmaf((float)(3 * l),     H, -6.0f)) - 50.0f, 0.0f);
        b = fmaxf(50.0f * expf(fmaf((float)(3 * l + 1), H, -6.0f)) - 50.0f, 0.0f);
        c = fmaxf(50.0f * expf(fmaf((float)(3 * l + 2), H, -6.0f)) - 50.0f, 0.0f);
    }

    // ---- load weight rows (guarded; out-of-range -> 0) ----
    float p[4][3] = {{0}}, r[3][3] = {{0}};
    if (act) {
        #pragma unroll
        for (int j = 0; j < 4; ++j) {
            int row = 3 * l - 1 + j;               // w5 rows 3l-1 .. 3l+2
            if (row >= 0 && row < 80) {
                p[j][0] = om5[3 * row]; p[j][1] = om5[3 * row + 1]; p[j][2] = om5[3 * row + 2];
            }
        }
        #pragma unroll
        for (int j = 0; j < 3; ++j) {
            int row = 3 * l - 1 + j;               // w6 rows 3l-1 .. 3l+1
            if (row >= 0 && row < 79) {
                r[j][0] = om6[3 * row]; r[j][1] = om6[3 * row + 1]; r[j][2] = om6[3 * row + 2];
            }
        }
    }

    // ---- fused per-node coefficients (computed once) ----
    float Ca[6] = {0}, Cb[6] = {0}, Cc[6] = {0};
    if (act) {
        make_coef(p[1], p[0], r[0], g1, g2, decay, Ca);  // node 3l
        make_coef(p[2], p[1], r[1], g1, g2, decay, Cb);  // node 3l+1
        make_coef(p[3], p[2], r[2], g1, g2, decay, Cc);  // node 3l+2
    }

    // ---- fold boundary conditions into coefficients ----
    if (l == 0) {
        // node 0 pinned to 0 forever
        #pragma unroll
        for (int j = 0; j < 6; ++j) Ca[j] = 0.0f;
        // ghost taps (u[-2], u[-1]) are exactly 0
        Cb[0] = 0.0f; Cb[1] = 0.0f;                      // node 1: bm, cm ghosts
        Cc[0] = 0.0f;                                    // node 2: cm ghost
    }
    if (l == 26) {
        // node 79 reads u[81] = 2*u[80] - u[79] = 2c - b : fold into b,c taps
        Cb[3] -= Cb[5];
        Cb[4] += 2.0f * Cb[5];
        Cb[5]  = 0.0f;
        // node 80 is overwritten by the BC every step
        #pragma unroll
        for (int j = 0; j < 6; ++j) Cc[j] = 0.0f;
    }

    // ---- right-BC recurrence: bc(t_n) = S_R - 50*exp(-0.1*t_n) ----
    float e = 1.0f;
    const float E0  = expf(-0.1f * DT);
    const float S_R = 50.0f * expf(1.5f);
    const bool is_bc = (l == 26);

    // ---- time stepping: 5 shuffles + 18 FMAs + 1 select per step ----
    #pragma unroll
    for (int s = 0; s < N_STEPS; ++s) {
        float am = __shfl_up_sync(FULLM, a, 1);    // u[3l-3]
        float bm = __shfl_up_sync(FULLM, b, 1);    // u[3l-2]
        float cm = __shfl_up_sync(FULLM, c, 1);    // u[3l-1]
        float ap = __shfl_down_sync(FULLM, a, 1);  // u[3l+3]
        float bp = __shfl_down_sync(FULLM, b, 1);  // u[3l+4]
        // (lane 0 / lane 26 garbage neighbors are multiplied by zero coeffs)

        e *= E0;

        float na = (fmaf(Ca[0], am, Ca[1] * bm) + fmaf(Ca[2], cm, Ca[3] * a))
                 + fmaf(Ca[4], b, Ca[5] * c);
        float nb = (fmaf(Cb[0], bm, Cb[1] * cm) + fmaf(Cb[2], a, Cb[3] * b))
                 + fmaf(Cb[4], c, Cb[5] * ap);
        float nc = (fmaf(Cc[0], cm, Cc[1] * a) + fmaf(Cc[2], b, Cc[3] * c))
                 + fmaf(Cc[4], ap, Cc[5] * bp);

        a = na;
        b = nb;
        c = is_bc ? fmaf(-50.0f, e, S_R) : nc;     // node 80 = BC(t_{n+1})
    }

    // ---- write result ----
    if (act) {
        out[3 * l]     = a;
        out[3 * l + 1] = b;
        out[3 * l + 2] = c;
    }
}

extern "C" void kernel_launch(void* const* d_in, const int* in_sizes, int n_in,
                              void* d_out, int out_size) {
    (void)in_sizes; (void)n_in; (void)out_size;
    const float* om5 = (const float*)d_in[0];   // omegas5 (80,3)
    const float* om6 = (const float*)d_in[1];   // omegas6 (79,3)
    float* out = (float*)d_out;                 // 81 floats
    weno_bs_kernel<<<1, 32>>>(om5, om6, out);
}

// round 8
// speedup vs baseline: 1.0048x; 1.0048x over previous
#include <cuda_runtime.h>

// WENO Black-Scholes stepper, M=80 (81 nodes), 26 Euler steps.
// Single step is affine: u'[k] = sum_{j=0..5} C_j[k] * u[k-3+j]  (+BC).
// We precompute the TWO-STEP composed operator E = A∘A (11 taps,
// E_m[k] = sum_{j+i=m} C_j[k]*C_i[k-3+j]) and run 13 double-steps.
// Boundary handling is fully algebraic:
//   - ghost/pinned node rows are zero rows  -> compose to zero automatically
//   - right ghost u[81]=2u[80]-u[79] folded into node 79's row
//   - intermediate-time BC u'[80]=bc(t_odd) enters u''[78],u''[79] via two
//     precomputed affine coefficients, folded into the FMA tree
// Loop body: 10 shuffles (one latency wave) + 36 FMAs + 2 muls + 1 select.

#define N_DBL 13
#define FULLM 0xFFFFFFFFu

// Fused 6-tap single-step coefficients for node k over u[k-3..k+2].
// p = w5 row k, q = w5 row k-1, r = w6 row k-1.
__device__ __forceinline__ void make_coef(const float* p, const float* q,
                                          const float* r, float g1, float g2,
                                          float decay, float* C)
{
    const float i6 = 1.0f / 6.0f;
    float A_2 = (2.0f * p[0]) * i6;
    float A_1 = (-7.0f * p[0] - p[1]) * i6;
    float A0  = (11.0f * p[0] + 5.0f * p[1] + 2.0f * p[2]) * i6;
    float A1  = (2.0f * p[1] + 5.0f * p[2]) * i6;
    float A2  = (-p[2]) * i6;
    float B_3 = (2.0f * q[0]) * i6;
    float B_2 = (-7.0f * q[0] - q[1]) * i6;
    float B_1 = (11.0f * q[0] + 5.0f * q[1] + 2.0f * q[2]) * i6;
    float B0  = (2.0f * q[1] + 5.0f * q[2]) * i6;
    float B1  = (-q[2]) * i6;
    C[0] = -g1 * B_3;
    C[1] = g1 * (A_2 - B_2) + g2 * r[0];
    C[2] = g1 * (A_1 - B_1) + g2 * (r[1] - 2.0f * r[0]);
    C[3] = g1 * (A0 - B0)   + g2 * (r[0] - 2.0f * r[1] + r[2]) + decay;
    C[4] = g1 * (A1 - B1)   + g2 * (r[1] - 2.0f * r[2]);
    C[5] = g1 * A2          + g2 * r[2];
}

// E[0..10] += contribution of own row C composed with neighbor rows R0..R5
// (R[j] = single-step row of node k-3+j).
__device__ __forceinline__ void compose(const float C[6],
                                        const float R0[6], const float R1[6],
                                        const float R2[6], const float R3[6],
                                        const float R4[6], const float R5[6],
                                        float E[11])
{
    #pragma unroll
    for (int m = 0; m < 11; ++m) E[m] = 0.0f;
    #pragma unroll
    for (int i = 0; i < 6; ++i) {
        E[0 + i] = fmaf(C[0], R0[i], E[0 + i]);
        E[1 + i] = fmaf(C[1], R1[i], E[1 + i]);
        E[2 + i] = fmaf(C[2], R2[i], E[2 + i]);
        E[3 + i] = fmaf(C[3], R3[i], E[3 + i]);
        E[4 + i] = fmaf(C[4], R4[i], E[4 + i]);
        E[5 + i] = fmaf(C[5], R5[i], E[5 + i]);
    }
}

__global__ void __launch_bounds__(32, 1)
weno_bs_kernel(const float* __restrict__ om5,   // (80,3) row-major
               const float* __restrict__ om6,   // (79,3) row-major
               float* __restrict__ out)         // 81 floats
{
    const int l = threadIdx.x;
    const bool act = (l <= 26);

    const float H     = 0.09375f;                 // exact in fp32
    const float DT    = (float)(1.0 / 26.0);
    const float g1    = DT * 0.055f / H;
    const float g2    = DT * 0.045f / (H * H);
    const float decay = 1.0f - DT * 0.1f;

    // ---- init u0 (one expf per lane + multiplicative e^H steps) ----
    float a = 0.f, b = 0.f, c = 0.f;
    if (act) {
        const float EH = expf(H);
        float ea = expf(fmaf((float)(3 * l), H, -6.0f));
        float eb = ea * EH;
        float ec = eb * EH;
        a = fmaxf(fmaf(50.0f, ea, -50.0f), 0.0f);
        b = fmaxf(fmaf(50.0f, eb, -50.0f), 0.0f);
        c = fmaxf(fmaf(50.0f, ec, -50.0f), 0.0f);
    }

    // ---- load weight rows (guarded; out-of-range -> 0) ----
    float p[4][3] = {{0}}, r[3][3] = {{0}};
    if (act) {
        #pragma unroll
        for (int j = 0; j < 4; ++j) {
            int row = 3 * l - 1 + j;               // w5 rows 3l-1 .. 3l+2
            if (row >= 0 && row < 80) {
                p[j][0] = om5[3 * row]; p[j][1] = om5[3 * row + 1]; p[j][2] = om5[3 * row + 2];
            }
        }
        #pragma unroll
        for (int j = 0; j < 3; ++j) {
            int row = 3 * l - 1 + j;               // w6 rows 3l-1 .. 3l+1
            if (row >= 0 && row < 79) {
                r[j][0] = om6[3 * row]; r[j][1] = om6[3 * row + 1]; r[j][2] = om6[3 * row + 2];
            }
        }
    }

    // ---- single-step per-node rows ----
    float Ca[6] = {0}, Cb[6] = {0}, Cc[6] = {0};
    if (act) {
        make_coef(p[1], p[0], r[0], g1, g2, decay, Ca);  // node 3l
        make_coef(p[2], p[1], r[1], g1, g2, decay, Cb);  // node 3l+1
        make_coef(p[3], p[2], r[2], g1, g2, decay, Cc);  // node 3l+2
    }

    // ---- fold boundaries into rows (makes them pure-linear / zero rows) ----
    if (l == 0) {
        #pragma unroll
        for (int j = 0; j < 6; ++j) Ca[j] = 0.0f;        // node 0 pinned to 0
        Cb[0] = 0.0f; Cb[1] = 0.0f;                      // ghost taps (u<0)=0
        Cc[0] = 0.0f;
    }
    if (l == 26) {
        Cb[3] -= Cb[5];                                  // fold u[81]=2u[80]-u[79]
        Cb[4] += 2.0f * Cb[5];
        Cb[5]  = 0.0f;
        #pragma unroll
        for (int j = 0; j < 6; ++j) Cc[j] = 0.0f;        // node 80 := BC each step
    }

    // affine coupling of intermediate BC into nodes 78/79 (lane 26 only)
    float CA80 = 0.f, CB80 = 0.f;
    if (l == 26) { CA80 = Ca[5]; CB80 = Cb[4]; }

    // ---- gather neighbor rows (one-time) ----
    float Am[6], Bm[6], Cm[6], Ap[6], Bp[6];
    #pragma unroll
    for (int j = 0; j < 6; ++j) {
        Am[j] = __shfl_up_sync(FULLM, Ca[j], 1);   // row 3l-3
        Bm[j] = __shfl_up_sync(FULLM, Cb[j], 1);   // row 3l-2
        Cm[j] = __shfl_up_sync(FULLM, Cc[j], 1);   // row 3l-1
        Ap[j] = __shfl_down_sync(FULLM, Ca[j], 1); // row 3l+3
        Bp[j] = __shfl_down_sync(FULLM, Cb[j], 1); // row 3l+4
    }
    // (lane 0's shfl_up self-rows and lane 26's zero rows from lane 27 are
    //  always multiplied by zero coefficients -> no explicit masking needed)

    // ---- composed 11-tap double-step operator ----
    float Ea[11], Eb[11], Ec[11];
    compose(Ca, Am, Bm, Cm, Ca, Cb, Cc, Ea);   // node 3l   : taps u[3l-6..3l+4]
    compose(Cb, Bm, Cm, Ca, Cb, Cc, Ap, Eb);   // node 3l+1 : taps u[3l-5..3l+5]
    compose(Cc, Cm, Ca, Cb, Cc, Ap, Bp, Ec);   // node 3l+2 : taps u[3l-4..3l+6]

    // ---- BC recurrences: bc(t)=S_R-50*exp(-0.1*t); e1 at odd, e2 at even steps
    const float E0  = expf(-0.1f * DT);
    const float E02 = E0 * E0;
    const float S_R = 50.0f * expf(1.5f);
    float e1 = E0, e2 = E02;
    const bool is_bc = (l == 26);

    // ---- 13 double-steps: 10 shuffles + 36-FMA trees + 1 select each ----
    #pragma unroll
    for (int s = 0; s < N_DBL; ++s) {
        float am2 = __shfl_up_sync(FULLM, a, 2);    // u[3l-6]
        float bm2 = __shfl_up_sync(FULLM, b, 2);    // u[3l-5]
        float cm2 = __shfl_up_sync(FULLM, c, 2);    // u[3l-4]
        float am  = __shfl_up_sync(FULLM, a, 1);    // u[3l-3]
        float bm  = __shfl_up_sync(FULLM, b, 1);    // u[3l-2]
        float cm  = __shfl_up_sync(FULLM, c, 1);    // u[3l-1]
        float ap  = __shfl_down_sync(FULLM, a, 1);  // u[3l+3]
        float bp  = __shfl_down_sync(FULLM, b, 1);  // u[3l+4]
        float cp  = __shfl_down_sync(FULLM, c, 1);  // u[3l+5]
        float ap2 = __shfl_down_sync(FULLM, a, 2);  // u[3l+6]

        float bc1 = fmaf(-50.0f, e1, S_R);          // BC at intermediate time
        float bc2 = fmaf(-50.0f, e2, S_R);          // BC at final time
        e1 *= E02;
        e2 *= E02;

        float na = ((fmaf(Ea[0], am2, Ea[1] * bm2) + fmaf(Ea[2], cm2, Ea[3] * am))
                  + (fmaf(Ea[4], bm, Ea[5] * cm)   + fmaf(Ea[6], a,  Ea[7] * b)))
                  + (fmaf(Ea[8], c, Ea[9] * ap)    + fmaf(Ea[10], bp, CA80 * bc1));

        float nb = ((fmaf(Eb[0], bm2, Eb[1] * cm2) + fmaf(Eb[2], am, Eb[3] * bm))
                  + (fmaf(Eb[4], cm, Eb[5] * a)    + fmaf(Eb[6], b,  Eb[7] * c)))
                  + (fmaf(Eb[8], ap, Eb[9] * bp)   + fmaf(Eb[10], cp, CB80 * bc1));

        float nc = ((fmaf(Ec[0], cm2, Ec[1] * am)  + fmaf(Ec[2], bm, Ec[3] * cm))
                  + (fmaf(Ec[4], a, Ec[5] * b)     + fmaf(Ec[6], c,  Ec[7] * ap)))
                  + (fmaf(Ec[8], bp, Ec[9] * cp)   + Ec[10] * ap2);

        a = na;
        b = nb;
        c = is_bc ? bc2 : nc;                       // node 80 = BC(t_even)
    }

    // ---- write result ----
    if (act) {
        out[3 * l]     = a;
        out[3 * l + 1] = b;
        out[3 * l + 2] = c;
    }
}

extern "C" void kernel_launch(void* const* d_in, const int* in_sizes, int n_in,
                              void* d_out, int out_size) {
    (void)in_sizes; (void)n_in; (void)out_size;
    const float* om5 = (const float*)d_in[0];   // omegas5 (80,3)
    const float* om6 = (const float*)d_in[1];   // omegas6 (79,3)
    float* out = (float*)d_out;                 // 81 floats
    weno_bs_kernel<<<1, 32>>>(om5, om6, out);
}

// round 9
// speedup vs baseline: 1.0146x; 1.0098x over previous
#include <cuda_runtime.h>

// WENO Black-Scholes stepper, M=80 (81 nodes), 26 Euler steps.
// Each timestep is affine in u: u_{n+1}[k] = sum_{j=-3}^{+2} C_j[k] * u[k+j],
// with C precomputed once from the fixed WENO weights. Lane l owns nodes
// {3l, 3l+1, 3l+2} (lanes 0..26). All boundary handling folded into the
// coefficients (zero rows / right-ghost fold); loop = 5 shuffles + 18 FMAs
// + 1 select per step. Weight loads are issued FIRST so the single cold
// DRAM wave overlaps the MUFU init and constant setup.

#define N_STEPS 26
#define FULLM 0xFFFFFFFFu

__global__ void __launch_bounds__(32, 1)
weno_bs_kernel(const float* __restrict__ om5,   // (80,3) row-major
               const float* __restrict__ om6,   // (79,3) row-major
               float* __restrict__ out)         // 81 floats
{
    const int l = threadIdx.x;
    const bool act = (l <= 26);

    // ---- issue all weight loads immediately (overlap DRAM with init math) ----
    // w5 rows 3l-1 .. 3l+2  -> p[0..3][0..2];  w6 rows 3l-1 .. 3l+1 -> r[0..2][..]
    float p[4][3] = {{0}}, r[3][3] = {{0}};
    if (act) {
        #pragma unroll
        for (int j = 0; j < 4; ++j) {
            int row = 3 * l - 1 + j;
            if (row >= 0 && row < 80) {
                p[j][0] = om5[3 * row]; p[j][1] = om5[3 * row + 1]; p[j][2] = om5[3 * row + 2];
            }
        }
        #pragma unroll
        for (int j = 0; j < 3; ++j) {
            int row = 3 * l - 1 + j;
            if (row >= 0 && row < 79) {
                r[j][0] = om6[3 * row]; r[j][1] = om6[3 * row + 1]; r[j][2] = om6[3 * row + 2];
            }
        }
    }

    const float H     = 0.09375f;                 // exact in fp32
    const float DT    = (float)(1.0 / 26.0);
    const float g1    = DT * 0.055f / H;          // DT*ADV/H
    const float g2    = DT * 0.045f / (H * H);    // DT*0.5*sigma^2/H^2
    const float decay = 1.0f - DT * 0.1f;

    // ---- init u0 while loads are in flight (one expf chain per lane) ----
    float a = 0.f, b = 0.f, c = 0.f;
    {
        const float EH = expf(H);
        float ea = expf(fmaf((float)(3 * l), H, -6.0f));
        float eb = ea * EH;
        float ec = eb * EH;
        a = fmaxf(fmaf(50.0f, ea, -50.0f), 0.0f);
        b = fmaxf(fmaf(50.0f, eb, -50.0f), 0.0f);
        c = fmaxf(fmaf(50.0f, ec, -50.0f), 0.0f);
        if (!act) { a = b = c = 0.f; }
    }

    // BC recurrence constants (independent of loads)
    const float E0  = expf(-0.1f * DT);
    const float S_R = 50.0f * expf(1.5f);
    float e = 1.0f;
    const bool is_bc = (l == 26);

    // ---- fused per-node 6-tap coefficients (once loads land) ----
    float Ca[6], Cb[6], Cc[6];
    {
        const float i6 = 1.0f / 6.0f;
        #pragma unroll
        for (int n = 0; n < 3; ++n) {
            const float* P = p[n + 1];   // w5 row k
            const float* Q = p[n];       // w5 row k-1
            const float* R = r[n];       // w6 row k-1
            float A_2 = (2.0f * P[0]) * i6;
            float A_1 = (-7.0f * P[0] - P[1]) * i6;
            float A0  = (11.0f * P[0] + 5.0f * P[1] + 2.0f * P[2]) * i6;
            float A1  = (2.0f * P[1] + 5.0f * P[2]) * i6;
            float A2  = (-P[2]) * i6;
            float B_3 = (2.0f * Q[0]) * i6;
            float B_2 = (-7.0f * Q[0] - Q[1]) * i6;
            float B_1 = (11.0f * Q[0] + 5.0f * Q[1] + 2.0f * Q[2]) * i6;
            float B0  = (2.0f * Q[1] + 5.0f * Q[2]) * i6;
            float B1  = (-Q[2]) * i6;
            float C0 = -g1 * B_3;
            float C1 = g1 * (A_2 - B_2) + g2 * R[0];
            float C2 = g1 * (A_1 - B_1) + g2 * (R[1] - 2.0f * R[0]);
            float C3 = g1 * (A0 - B0)   + g2 * (R[0] - 2.0f * R[1] + R[2]) + decay;
            float C4 = g1 * (A1 - B1)   + g2 * (R[1] - 2.0f * R[2]);
            float C5 = g1 * A2          + g2 * R[2];
            float* C = (n == 0) ? Ca : (n == 1) ? Cb : Cc;
            C[0] = C0; C[1] = C1; C[2] = C2; C[3] = C3; C[4] = C4; C[5] = C5;
        }
    }

    // ---- fold boundary conditions into coefficients ----
    if (l == 0) {
        #pragma unroll
        for (int j = 0; j < 6; ++j) Ca[j] = 0.0f;        // node 0 pinned to 0
        Cb[0] = 0.0f; Cb[1] = 0.0f;                      // left ghosts == 0
        Cc[0] = 0.0f;
    }
    if (l == 26) {
        Cb[3] -= Cb[5];                                  // u[81] = 2u[80]-u[79]
        Cb[4] += 2.0f * Cb[5];
        Cb[5]  = 0.0f;
        #pragma unroll
        for (int j = 0; j < 6; ++j) Cc[j] = 0.0f;        // node 80 := BC each step
    }
    if (!act) {
        #pragma unroll
        for (int j = 0; j < 6; ++j) { Ca[j] = 0.f; Cb[j] = 0.f; Cc[j] = 0.f; }
    }

    // ---- time stepping: 5 shuffles + 18 FMAs + 1 select per step ----
    #pragma unroll
    for (int s = 0; s < N_STEPS; ++s) {
        float am = __shfl_up_sync(FULLM, a, 1);    // u[3l-3]
        float bm = __shfl_up_sync(FULLM, b, 1);    // u[3l-2]
        float cm = __shfl_up_sync(FULLM, c, 1);    // u[3l-1]
        float ap = __shfl_down_sync(FULLM, a, 1);  // u[3l+3]
        float bp = __shfl_down_sync(FULLM, b, 1);  // u[3l+4]
        // lane-0 / lane-26 garbage neighbors hit zero coefficients

        e *= E0;

        float na = (fmaf(Ca[0], am, Ca[1] * bm) + fmaf(Ca[2], cm, Ca[3] * a))
                 + fmaf(Ca[4], b, Ca[5] * c);
        float nb = (fmaf(Cb[0], bm, Cb[1] * cm) + fmaf(Cb[2], a, Cb[3] * b))
                 + fmaf(Cb[4], c, Cb[5] * ap);
        float nc = (fmaf(Cc[0], cm, Cc[1] * a) + fmaf(Cc[2], b, Cc[3] * c))
                 + fmaf(Cc[4], ap, Cc[5] * bp);

        a = na;
        b = nb;
        c = is_bc ? fmaf(-50.0f, e, S_R) : nc;     // node 80 = BC(t_{n+1})
    }

    // ---- write result ----
    if (act) {
        out[3 * l]     = a;
        out[3 * l + 1] = b;
        out[3 * l + 2] = c;
    }
}

extern "C" void kernel_launch(void* const* d_in, const int* in_sizes, int n_in,
                              void* d_out, int out_size) {
    (void)in_sizes; (void)n_in; (void)out_size;
    const float* om5 = (const float*)d_in[0];   // omegas5 (80,3)
    const float* om6 = (const float*)d_in[1];   // omegas6 (79,3)
    float* out = (float*)d_out;                 // 81 floats
    weno_bs_kernel<<<1, 32>>>(om5, om6, out);
}